// round 3
// baseline (speedup 1.0000x reference)
#include <cuda_runtime.h>
#include <cstdint>

#define HID   256
#define BB    8
#define TT    16
#define INSZ  784
#define OUTSZ 128
#define NC    32        // GRU persistent CTAs

// scratch (no device allocs allowed)
__device__ float g_seq[TT * BB * INSZ];       // [t][b][784]
__device__ float g_gi [TT * BB * 3 * HID];    // [t][b][768]
__device__ float g_h  [2][BB * HID];          // double-buffered hidden state
__device__ unsigned g_bar_ctr;                // monotonic grid barrier counter

// ---------------- f32x2 helpers ----------------
__device__ __forceinline__ unsigned long long pk2(float a, float b) {
    unsigned long long r;
    asm("mov.b64 %0, {%1,%2};" : "=l"(r) : "f"(a), "f"(b));
    return r;
}
__device__ __forceinline__ float2 upk2(unsigned long long v) {
    float2 f;
    asm("mov.b64 {%0,%1}, %2;" : "=f"(f.x), "=f"(f.y) : "l"(v));
    return f;
}
__device__ __forceinline__ void ffma2(unsigned long long& d,
                                      unsigned long long a,
                                      unsigned long long b) {
    asm("fma.rn.f32x2 %0, %1, %2, %0;" : "+l"(d) : "l"(a), "l"(b));
}
__device__ __forceinline__ float sigm(float x) {
    return 1.0f / (1.0f + __expf(-x));
}
__device__ __forceinline__ float tanh_fast(float x) {
    return 2.0f / (1.0f + __expf(-2.0f * x)) - 1.0f;
}

// =====================================================================
// Kernel 1: fused 3D+2D adaptive avg pool = mean over [2 x 16 x 16]
// blocks. One warp per (b,c,d2,h2). Lanes 0..27 own one float4 column
// each (4 lanes -> one of 7 w-bins), coalesced 448B row reads.
// =====================================================================
__global__ void pool_kernel(const float* __restrict__ x) {
    int gwarp = (blockIdx.x * blockDim.x + threadIdx.x) >> 5;
    int lane  = threadIdx.x & 31;

    int h2 = gwarp % 7;  int tmp = gwarp / 7;
    int d2 = tmp % 16;   tmp /= 16;
    int c  = tmp % 16;   tmp /= 16;
    int b  = tmp;        // 0..7

    const float* base = x + (((long long)(b * 16 + c) * 32 + d2 * 2) * 112
                             + h2 * 16) * 112;
    float acc0 = 0.0f, acc1 = 0.0f;
    if (lane < 28) {
        #pragma unroll
        for (int dd = 0; dd < 2; dd++) {
            #pragma unroll 8
            for (int hh = 0; hh < 16; hh += 2) {
                const float4* r0 = (const float4*)(base + dd * 12544 + hh * 112);
                const float4* r1 = (const float4*)(base + dd * 12544 + (hh + 1) * 112);
                float4 v0 = r0[lane];
                float4 v1 = r1[lane];
                acc0 += (v0.x + v0.y) + (v0.z + v0.w);
                acc1 += (v1.x + v1.y) + (v1.z + v1.w);
            }
        }
    }
    float acc = acc0 + acc1;
    acc += __shfl_down_sync(0xffffffffu, acc, 2);
    acc += __shfl_down_sync(0xffffffffu, acc, 1);
    if (lane < 28 && (lane & 3) == 0) {
        int w2 = lane >> 2;
        g_seq[(d2 * BB + b) * INSZ + c * 49 + h2 * 7 + w2] = acc * (1.0f / 512.0f);
    }
}

// =====================================================================
// Kernel 2: gi = seq @ W_ih^T + b_ih for all 16 steps at once.
// C[128,768] = A[128,784] * B[768,784]^T. 32(tb) x 32(g) tiles, kc=16.
// grid (24, 4), 256 threads.
// =====================================================================
__global__ void gi_kernel(const float* __restrict__ Wih,
                          const float* __restrict__ bih) {
    __shared__ float Ash[32][17];
    __shared__ float Bsh[32][17];

    int tid = threadIdx.x;
    int g0  = blockIdx.x * 32;
    int tb0 = blockIdx.y * 32;
    int tb  = tid & 31;
    int wid = tid >> 5;               // 0..7

    unsigned long long acc[4];
    #pragma unroll
    for (int i = 0; i < 4; i++) acc[i] = 0ull;

    for (int kc = 0; kc < 49; kc++) {
        int k0 = kc * 16;
        #pragma unroll
        for (int i = tid; i < 512; i += 256) {
            int r = i >> 4, k = i & 15;
            Ash[r][k] = g_seq[(tb0 + r) * INSZ + k0 + k];
            Bsh[r][k] = Wih[(long long)(g0 + r) * INSZ + k0 + k];
        }
        __syncthreads();
        #pragma unroll
        for (int k = 0; k < 16; k += 2) {
            unsigned long long a2 = pk2(Ash[tb][k], Ash[tb][k + 1]);
            #pragma unroll
            for (int i = 0; i < 4; i++) {
                int gr = wid + 8 * i;
                ffma2(acc[i], a2, pk2(Bsh[gr][k], Bsh[gr][k + 1]));
            }
        }
        __syncthreads();
    }
    #pragma unroll
    for (int i = 0; i < 4; i++) {
        int g = g0 + wid + 8 * i;
        float2 f = upk2(acc[i]);
        g_gi[(tb0 + tb) * (3 * HID) + g] = f.x + f.y + bih[g];
    }
}

// =====================================================================
// Kernel 3: persistent GRU (16 steps) + output head.
// 32 CTAs x 128 threads. Thread (jl = tid>>4 in [0,8), ks = tid&15).
// CTA c owns hidden units j = c*8 + jl. Each thread keeps its W_hh
// slice (3 gates x 16 k) as 24 f32x2 pairs IN REGISTERS for all steps.
// h exchanged via double-buffered g_h + monotonic gmem grid barrier.
// h staged in smem as 16x8 pair-transpose: pair p -> slot ((p&15)<<3)|(p>>4)
// so lanes (distinct ks) hit distinct banks on ld.shared.b64.
// =====================================================================
__global__ void __launch_bounds__(128, 1)
gru_kernel(const float* __restrict__ Whh,
           const float* __restrict__ bhh,
           const float* __restrict__ Wout,
           const float* __restrict__ bout,
           float* __restrict__ out) {
    __shared__ unsigned long long hsm[BB * 132];   // 8 rows x 128 slots (+4 pad)

    int tid = threadIdx.x;
    int c   = blockIdx.x;
    int jl  = tid >> 4;          // 0..7
    int ks  = tid & 15;          // 0..15
    int j   = c * 8 + jl;        // hidden unit owned

    // --- load W_hh slice into registers (once) ---
    unsigned long long wp[3][8];
    #pragma unroll
    for (int g = 0; g < 3; g++) {
        const ulonglong2* ws =
            (const ulonglong2*)(Whh + (long long)(g * HID + j) * HID + ks * 16);
        #pragma unroll
        for (int i = 0; i < 4; i++) {
            ulonglong2 v = ws[i];
            wp[g][2 * i]     = v.x;
            wp[g][2 * i + 1] = v.y;
        }
    }
    float bh0 = bhh[j], bh1 = bhh[HID + j], bh2 = bhh[2 * HID + j];

    int base2 = ((ks & 1) << 6) + (ks >> 1);   // slot base for this ks

    for (int t = 0; t < TT; t++) {
        // ---- stage h(t) into smem ----
        if (t == 0) {
            #pragma unroll
            for (int s = tid; s < BB * 132; s += 128) hsm[s] = 0ull;
        } else {
            int buf = t & 1;
            #pragma unroll
            for (int s = tid; s < 1024; s += 128) {
                int b  = s >> 7;
                int sl = s & 127;
                int p  = ((sl & 7) << 4) | (sl >> 3);   // inverse transpose
                float2 v = ((const float2*)(g_h[buf] + b * HID))[p];
                hsm[b * 132 + sl] = pk2(v.x, v.y);
            }
        }
        __syncthreads();

        // ---- prefetch gi + hprev (ks==0 threads only) ----
        float gir[BB], giz[BB], gin[BB], hpv[BB];
        if (ks == 0) {
            #pragma unroll
            for (int b = 0; b < BB; b++) {
                const float* gp = g_gi + (long long)(t * BB + b) * (3 * HID) + j;
                gir[b] = gp[0];
                giz[b] = gp[HID];
                gin[b] = gp[2 * HID];
                hpv[b] = (t == 0) ? 0.0f : g_h[t & 1][b * HID + j];
            }
        }

        // ---- partial dots: 3 gates x 8 batches over this thread's k-slice ----
        unsigned long long acc[3][BB];
        #pragma unroll
        for (int g = 0; g < 3; g++)
            #pragma unroll
            for (int b = 0; b < BB; b++) acc[g][b] = 0ull;

        #pragma unroll
        for (int b = 0; b < BB; b++) {
            const unsigned long long* hb = hsm + b * 132 + base2;
            #pragma unroll
            for (int i = 0; i < 8; i++) {
                unsigned long long h2 = hb[i << 3];
                ffma2(acc[0][b], wp[0][i], h2);
                ffma2(acc[1][b], wp[1][i], h2);
                ffma2(acc[2][b], wp[2][i], h2);
            }
        }

        // ---- reduce over ks (16 lanes) ----
        float red[3][BB];
        #pragma unroll
        for (int g = 0; g < 3; g++) {
            #pragma unroll
            for (int b = 0; b < BB; b++) {
                float2 f = upk2(acc[g][b]);
                float v = f.x + f.y;
                v += __shfl_down_sync(0xffffffffu, v, 8, 16);
                v += __shfl_down_sync(0xffffffffu, v, 4, 16);
                v += __shfl_down_sync(0xffffffffu, v, 2, 16);
                v += __shfl_down_sync(0xffffffffu, v, 1, 16);
                red[g][b] = v;
            }
        }

        // ---- gate math + store h(t+1) (ks==0) ----
        if (ks == 0) {
            int buf1 = (t + 1) & 1;
            #pragma unroll
            for (int b = 0; b < BB; b++) {
                float hr = red[0][b] + bh0;
                float hz = red[1][b] + bh1;
                float hn = red[2][b] + bh2;
                float r = sigm(gir[b] + hr);
                float z = sigm(giz[b] + hz);
                float n = tanh_fast(gin[b] + r * hn);
                float hnew = n + z * (hpv[b] - n);
                g_h[buf1][b * HID + j] = hnew;
            }
        }

        // ---- grid barrier (monotonic, wrap-safe) ----
        __threadfence();
        __syncthreads();
        if (tid == 0) {
            unsigned ticket = atomicAdd(&g_bar_ctr, 1u);
            unsigned goal = (ticket / NC + 1u) * NC;
            unsigned v;
            do {
                asm volatile("ld.global.acquire.gpu.u32 %0, [%1];"
                             : "=r"(v) : "l"(&g_bar_ctr));
                if ((int)(v - goal) >= 0) break;
                __nanosleep(64);
            } while (true);
        }
        __syncthreads();
    }

    // ---- output head: h final in g_h[0]; CTA c -> outputs [c*4, c*4+4) ----
    {
        int q  = tid & 3;            // k-quarter
        int b  = (tid >> 2) & 7;
        int ol = tid >> 5;           // 0..3
        int o  = c * 4 + ol;
        const float4* wv = (const float4*)(Wout + (long long)o * HID + q * 64);
        const float4* hv = (const float4*)(g_h[0] + b * HID + q * 64);
        float a = 0.0f;
        #pragma unroll
        for (int i = 0; i < 16; i++) {
            float4 w = wv[i];
            float4 h = hv[i];
            a += w.x * h.x + w.y * h.y + w.z * h.z + w.w * h.w;
        }
        a += __shfl_down_sync(0xffffffffu, a, 2, 4);
        a += __shfl_down_sync(0xffffffffu, a, 1, 4);
        if (q == 0) out[b * OUTSZ + o] = a + bout[o];
    }
}

// =====================================================================
extern "C" void kernel_launch(void* const* d_in, const int* in_sizes, int n_in,
                              void* d_out, int out_size) {
    const float* x    = (const float*)d_in[0];
    const float* Wih  = (const float*)d_in[1];
    const float* Whh  = (const float*)d_in[2];
    const float* bih  = (const float*)d_in[3];
    const float* bhh  = (const float*)d_in[4];
    const float* Wout = (const float*)d_in[5];
    const float* bout = (const float*)d_in[6];
    float* out = (float*)d_out;

    pool_kernel<<<1792, 256>>>(x);                 // 14336 warps
    gi_kernel<<<dim3(24, 4), 256>>>(Wih, bih);
    gru_kernel<<<NC, 128>>>(Whh, bhh, Wout, bout, out);
}

// round 5
// speedup vs baseline: 1.4482x; 1.4482x over previous
#include <cuda_runtime.h>
#include <cstdint>

#define HID   256
#define BB    8
#define TT    16
#define INSZ  784
#define OUTSZ 128

// scratch (no device allocs allowed)
__device__ float g_seq[TT * BB * INSZ];       // [t][b][784]
__device__ float g_gi [TT * BB * 3 * HID];    // [t][b][768]

// ---------------- f32x2 helpers ----------------
__device__ __forceinline__ unsigned long long pk2(float a, float b) {
    unsigned long long r;
    asm("mov.b64 %0, {%1,%2};" : "=l"(r) : "f"(a), "f"(b));
    return r;
}
__device__ __forceinline__ float2 upk2(unsigned long long v) {
    float2 f;
    asm("mov.b64 {%0,%1}, %2;" : "=f"(f.x), "=f"(f.y) : "l"(v));
    return f;
}
__device__ __forceinline__ void ffma2(unsigned long long& d,
                                      unsigned long long a,
                                      unsigned long long b) {
    asm("fma.rn.f32x2 %0, %1, %2, %0;" : "+l"(d) : "l"(a), "l"(b));
}
__device__ __forceinline__ uint32_t smem_u32(const void* p) {
    uint32_t a;
    asm("{ .reg .u64 t; cvta.to.shared.u64 t, %1; cvt.u32.u64 %0, t; }"
        : "=r"(a) : "l"(p));
    return a;
}
__device__ __forceinline__ void st_cluster_f32(uint32_t saddr, int rank, float v) {
    asm volatile(
        "{ .reg .b32 ra; mapa.shared::cluster.u32 ra, %0, %1; "
        "st.shared::cluster.f32 [ra], %2; }"
        :: "r"(saddr), "r"(rank), "f"(v) : "memory");
}
__device__ __forceinline__ void cluster_sync_() {
    asm volatile("barrier.cluster.arrive.aligned;" ::: "memory");
    asm volatile("barrier.cluster.wait.aligned;"   ::: "memory");
}
__device__ __forceinline__ float sigm(float x) {
    return 1.0f / (1.0f + __expf(-x));
}
__device__ __forceinline__ float tanh_fast(float x) {
    return 2.0f / (1.0f + __expf(-2.0f * x)) - 1.0f;
}

// =====================================================================
// Kernel 1: fused 3D+2D adaptive avg pool (R3-proven version).
// One warp per (b,c,d2,h2). Lanes 0..27 own one float4 column each.
// =====================================================================
__global__ void pool_kernel(const float* __restrict__ x) {
    int gwarp = (blockIdx.x * blockDim.x + threadIdx.x) >> 5;
    int lane  = threadIdx.x & 31;

    int h2 = gwarp % 7;  int tmp = gwarp / 7;
    int d2 = tmp % 16;   tmp /= 16;
    int c  = tmp % 16;   tmp /= 16;
    int b  = tmp;        // 0..7

    const float* base = x + (((long long)(b * 16 + c) * 32 + d2 * 2) * 112
                             + h2 * 16) * 112;
    float acc0 = 0.0f, acc1 = 0.0f;
    if (lane < 28) {
        #pragma unroll
        for (int dd = 0; dd < 2; dd++) {
            #pragma unroll 8
            for (int hh = 0; hh < 16; hh += 2) {
                const float4* r0 = (const float4*)(base + dd * 12544 + hh * 112);
                const float4* r1 = (const float4*)(base + dd * 12544 + (hh + 1) * 112);
                float4 v0 = r0[lane];
                float4 v1 = r1[lane];
                acc0 += (v0.x + v0.y) + (v0.z + v0.w);
                acc1 += (v1.x + v1.y) + (v1.z + v1.w);
            }
        }
    }
    float acc = acc0 + acc1;
    acc += __shfl_down_sync(0xffffffffu, acc, 2);
    acc += __shfl_down_sync(0xffffffffu, acc, 1);
    if (lane < 28 && (lane & 3) == 0) {
        int w2 = lane >> 2;
        g_seq[(d2 * BB + b) * INSZ + c * 49 + h2 * 7 + w2] = acc * (1.0f / 512.0f);
    }
}

// =====================================================================
// Kernel 2: gi = seq @ W_ih^T + b_ih (R3-proven version).
// grid (24, 4), 256 threads.
// =====================================================================
__global__ void gi_kernel(const float* __restrict__ Wih,
                          const float* __restrict__ bih) {
    __shared__ float Ash[32][17];
    __shared__ float Bsh[32][17];

    int tid = threadIdx.x;
    int g0  = blockIdx.x * 32;
    int tb0 = blockIdx.y * 32;
    int tb  = tid & 31;
    int wid = tid >> 5;               // 0..7

    unsigned long long acc[4];
    #pragma unroll
    for (int i = 0; i < 4; i++) acc[i] = 0ull;

    for (int kc = 0; kc < 49; kc++) {
        int k0 = kc * 16;
        #pragma unroll
        for (int i = tid; i < 512; i += 256) {
            int r = i >> 4, k = i & 15;
            Ash[r][k] = g_seq[(tb0 + r) * INSZ + k0 + k];
            Bsh[r][k] = Wih[(long long)(g0 + r) * INSZ + k0 + k];
        }
        __syncthreads();
        #pragma unroll
        for (int k = 0; k < 16; k += 2) {
            unsigned long long a2 = pk2(Ash[tb][k], Ash[tb][k + 1]);
            #pragma unroll
            for (int i = 0; i < 4; i++) {
                int gr = wid + 8 * i;
                ffma2(acc[i], a2, pk2(Bsh[gr][k], Bsh[gr][k + 1]));
            }
        }
        __syncthreads();
    }
    #pragma unroll
    for (int i = 0; i < 4; i++) {
        int g = g0 + wid + 8 * i;
        float2 f = upk2(acc[i]);
        g_gi[(tb0 + tb) * (3 * HID) + g] = f.x + f.y + bih[g];
    }
}

// =====================================================================
// Kernel 3: GRU, one 8-CTA cluster PER BATCH (8 clusters, 64 CTAs).
// The recurrence is batch-independent, so all sync stays inside a
// cluster (DSMEM + barrier.cluster), no global coherence needed.
// CTA rank owns units j in [rank*32, rank*32+32). Thread (jl = tid>>3,
// ks = tid&7): W_hh slice (3 gates x 32 k) in 48 f32x2 register pairs.
// h in local smem, swizzled: pair p at slot ((p&15)<<3)|(p>>4) so the
// (ks) lane pattern is bank-conflict-free for LDS.64.
// Producers (ks==0) push h_new to all 8 peers via st.shared::cluster.
// =====================================================================
__global__ void __launch_bounds__(256, 1) __cluster_dims__(8, 1, 1)
gru_kernel(const float* __restrict__ Whh,
           const float* __restrict__ bhh,
           const float* __restrict__ Wout,
           const float* __restrict__ bout,
           float* __restrict__ out) {
    __shared__ float hs[2][264];     // double-buffered h (swizzled), 256+pad

    int tid  = threadIdx.x;
    int b    = blockIdx.x >> 3;      // batch = cluster id
    int rank = blockIdx.x & 7;       // cluster rank
    int jl   = tid >> 3;             // 0..31
    int ks   = tid & 7;              // 0..7
    int j    = rank * 32 + jl;       // owned hidden unit

    // --- W_hh slice into registers: gate g, k = ks*32 .. ks*32+31 ---
    unsigned long long wp[3][16];
    #pragma unroll
    for (int g = 0; g < 3; g++) {
        const ulonglong2* ws =
            (const ulonglong2*)(Whh + (long long)(g * HID + j) * HID + ks * 32);
        #pragma unroll
        for (int m = 0; m < 8; m++) {
            ulonglong2 v = ws[m];
            wp[g][2 * m]     = v.x;
            wp[g][2 * m + 1] = v.y;
        }
    }
    float bh0 = bhh[j], bh1 = bhh[HID + j], bh2 = bhh[2 * HID + j];
    float hpv = 0.0f;                // hprev for owned (b, j): scalar

    // zero both h buffers, then cluster-wide rendezvous
    for (int s = tid; s < 2 * 264; s += 256) (&hs[0][0])[s] = 0.0f;
    __syncthreads();
    cluster_sync_();

    for (int t = 0; t < TT; t++) {
        const unsigned long long* hb = (const unsigned long long*)hs[t & 1];

        // prefetch gi for the owned unit (hide L2 latency under the dot)
        float gir = 0.0f, giz = 0.0f, gin = 0.0f;
        if (ks == 0) {
            const float* gp = g_gi + (long long)(t * BB + b) * (3 * HID) + j;
            gir = gp[0];
            giz = gp[HID];
            gin = gp[2 * HID];
        }

        // partial dots over k = ks*32..ks*32+31 (pairs p = 16*ks + i)
        unsigned long long a0 = 0, a1 = 0, a2 = 0;
        #pragma unroll
        for (int i = 0; i < 16; i++) {
            unsigned long long h2 = hb[(i << 3) | ks];
            ffma2(a0, wp[0][i], h2);
            ffma2(a1, wp[1][i], h2);
            ffma2(a2, wp[2][i], h2);
        }
        float2 f;
        f = upk2(a0);  float v0 = f.x + f.y;
        f = upk2(a1);  float v1 = f.x + f.y;
        f = upk2(a2);  float v2 = f.x + f.y;
        #pragma unroll
        for (int d = 4; d >= 1; d >>= 1) {
            v0 += __shfl_down_sync(0xffffffffu, v0, d, 8);
            v1 += __shfl_down_sync(0xffffffffu, v1, d, 8);
            v2 += __shfl_down_sync(0xffffffffu, v2, d, 8);
        }

        if (ks == 0) {
            float r = sigm(gir + v0 + bh0);
            float z = sigm(giz + v1 + bh1);
            float n = tanh_fast(gin + r * (v2 + bh2));
            float hnew = n + z * (hpv - n);
            hpv = hnew;
            // swizzled float index for h[j] in next buffer
            int p    = j >> 1;
            int slot = ((p & 15) << 3) | (p >> 4);
            int fidx = 2 * slot + (j & 1);
            uint32_t la = smem_u32(&hs[(t + 1) & 1][fidx]);
            #pragma unroll
            for (int pr = 0; pr < 8; pr++) st_cluster_f32(la, pr, hnew);
        }

        cluster_sync_();
    }

    // ---- output head: final h (t=16) is in local hs[0] of every CTA.
    // CTA rank -> outputs o = rank*16 + ol; thread (ol = tid>>4, kq = tid&15)
    {
        int ol = tid >> 4;           // 0..15
        int kq = tid & 15;           // 0..15
        int o  = rank * 16 + ol;
        const float* wo = Wout + (long long)o * HID;
        float a = 0.0f;
        #pragma unroll
        for (int m = 0; m < 16; m++) {
            int k    = kq * 16 + m;
            int p    = k >> 1;
            int slot = ((p & 15) << 3) | (p >> 4);
            a += wo[k] * hs[0][2 * slot + (k & 1)];
        }
        a += __shfl_down_sync(0xffffffffu, a, 8, 16);
        a += __shfl_down_sync(0xffffffffu, a, 4, 16);
        a += __shfl_down_sync(0xffffffffu, a, 2, 16);
        a += __shfl_down_sync(0xffffffffu, a, 1, 16);
        if (kq == 0) out[b * OUTSZ + o] = a + bout[o];
    }
}

// =====================================================================
extern "C" void kernel_launch(void* const* d_in, const int* in_sizes, int n_in,
                              void* d_out, int out_size) {
    const float* x    = (const float*)d_in[0];
    const float* Wih  = (const float*)d_in[1];
    const float* Whh  = (const float*)d_in[2];
    const float* bih  = (const float*)d_in[3];
    const float* bhh  = (const float*)d_in[4];
    const float* Wout = (const float*)d_in[5];
    const float* bout = (const float*)d_in[6];
    float* out = (float*)d_out;

    pool_kernel<<<1792, 256>>>(x);                 // 14336 warps
    gi_kernel<<<dim3(24, 4), 256>>>(Wih, bih);
    gru_kernel<<<64, 256>>>(Whh, bhh, Wout, bout, out);   // 8 clusters x 8 CTAs
}

// round 6
// speedup vs baseline: 2.0051x; 1.3846x over previous
#include <cuda_runtime.h>
#include <cstdint>

#define HID   256
#define BB    8
#define TT    16
#define INSZ  784
#define OUTSZ 128

// scratch (no device allocs allowed)
__device__ float g_seq[TT * BB * INSZ];       // [t][b][784]
__device__ float g_gi [TT * BB * 3 * HID];    // [t][b][768]

// ---------------- f32x2 helpers ----------------
__device__ __forceinline__ unsigned long long pk2(float a, float b) {
    unsigned long long r;
    asm("mov.b64 %0, {%1,%2};" : "=l"(r) : "f"(a), "f"(b));
    return r;
}
__device__ __forceinline__ float2 upk2(unsigned long long v) {
    float2 f;
    asm("mov.b64 {%0,%1}, %2;" : "=f"(f.x), "=f"(f.y) : "l"(v));
    return f;
}
__device__ __forceinline__ void ffma2(unsigned long long& d,
                                      unsigned long long a,
                                      unsigned long long b) {
    asm("fma.rn.f32x2 %0, %1, %2, %0;" : "+l"(d) : "l"(a), "l"(b));
}
__device__ __forceinline__ uint32_t smem_u32(const void* p) {
    uint32_t a;
    asm("{ .reg .u64 t; cvta.to.shared.u64 t, %1; cvt.u32.u64 %0, t; }"
        : "=r"(a) : "l"(p));
    return a;
}
__device__ __forceinline__ void st_cluster_f32(uint32_t saddr, int rank, float v) {
    asm volatile(
        "{ .reg .b32 ra; mapa.shared::cluster.u32 ra, %0, %1; "
        "st.shared::cluster.f32 [ra], %2; }"
        :: "r"(saddr), "r"(rank), "f"(v) : "memory");
}
__device__ __forceinline__ void cluster_sync_() {
    asm volatile("barrier.cluster.arrive.aligned;" ::: "memory");
    asm volatile("barrier.cluster.wait.aligned;"   ::: "memory");
}
__device__ __forceinline__ float sigm(float x) {
    return 1.0f / (1.0f + __expf(-x));
}
__device__ __forceinline__ float tanh_fast(float x) {
    return 2.0f / (1.0f + __expf(-2.0f * x)) - 1.0f;
}

// =====================================================================
// Kernel 1: fused 3D+2D adaptive avg pool (R3-proven + streaming loads).
// One warp per (b,c,d2,h2). Lanes 0..27 own one float4 column each.
// =====================================================================
__global__ void pool_kernel(const float* __restrict__ x) {
    int gwarp = (blockIdx.x * blockDim.x + threadIdx.x) >> 5;
    int lane  = threadIdx.x & 31;

    int h2 = gwarp % 7;  int tmp = gwarp / 7;
    int d2 = tmp % 16;   tmp /= 16;
    int c  = tmp % 16;   tmp /= 16;
    int b  = tmp;        // 0..7

    const float* base = x + (((long long)(b * 16 + c) * 32 + d2 * 2) * 112
                             + h2 * 16) * 112;
    float acc0 = 0.0f, acc1 = 0.0f;
    if (lane < 28) {
        #pragma unroll
        for (int dd = 0; dd < 2; dd++) {
            #pragma unroll 8
            for (int hh = 0; hh < 16; hh += 2) {
                const float4* r0 = (const float4*)(base + dd * 12544 + hh * 112);
                const float4* r1 = (const float4*)(base + dd * 12544 + (hh + 1) * 112);
                float4 v0 = __ldcs(r0 + lane);
                float4 v1 = __ldcs(r1 + lane);
                acc0 += (v0.x + v0.y) + (v0.z + v0.w);
                acc1 += (v1.x + v1.y) + (v1.z + v1.w);
            }
        }
    }
    float acc = acc0 + acc1;
    acc += __shfl_down_sync(0xffffffffu, acc, 2);
    acc += __shfl_down_sync(0xffffffffu, acc, 1);
    if (lane < 28 && (lane & 3) == 0) {
        int w2 = lane >> 2;
        g_seq[(d2 * BB + b) * INSZ + c * 49 + h2 * 7 + w2] = acc * (1.0f / 512.0f);
    }
}

// =====================================================================
// Kernel 2: gi = seq @ W_ih^T + b_ih for all 16 steps.
// C[128,768] = A[128,784] * B[768,784]^T. 32(tb) x 32(g) tiles.
// k-chunk 56 (14 iters), double-buffered smem + register prefetch,
// 64-bit smem reads feeding fma.rn.f32x2. grid (24, 4), 256 threads.
// =====================================================================
__global__ void gi_kernel(const float* __restrict__ Wih,
                          const float* __restrict__ bih) {
    __shared__ __align__(16) float Ash[2][32][58];
    __shared__ __align__(16) float Bsh[2][32][58];

    int tid = threadIdx.x;
    int g0  = blockIdx.x * 32;
    int tb0 = blockIdx.y * 32;
    int tb  = tid & 31;
    int wid = tid >> 5;               // 0..7

    // preload tile 0
    #pragma unroll
    for (int m = 0; m < 7; m++) {
        int i = tid + 256 * m;
        int r = i / 56, k = i % 56;
        Ash[0][r][k] = g_seq[(tb0 + r) * INSZ + k];
        Bsh[0][r][k] = Wih[(long long)(g0 + r) * INSZ + k];
    }
    __syncthreads();

    unsigned long long acc[4] = {0ull, 0ull, 0ull, 0ull};
    float ra[7], rb[7];

    for (int it = 0; it < 14; it++) {
        int cur = it & 1, nxt = cur ^ 1;
        if (it < 13) {
            int k0 = (it + 1) * 56;
            #pragma unroll
            for (int m = 0; m < 7; m++) {
                int i = tid + 256 * m;
                int r = i / 56, k = i % 56;
                ra[m] = g_seq[(tb0 + r) * INSZ + k0 + k];
                rb[m] = Wih[(long long)(g0 + r) * INSZ + k0 + k];
            }
        }
        // compute on current buffer
        const unsigned long long* Ar = (const unsigned long long*)Ash[cur][tb];
        const unsigned long long* B0 = (const unsigned long long*)Bsh[cur][wid];
        const unsigned long long* B1 = (const unsigned long long*)Bsh[cur][wid + 8];
        const unsigned long long* B2 = (const unsigned long long*)Bsh[cur][wid + 16];
        const unsigned long long* B3 = (const unsigned long long*)Bsh[cur][wid + 24];
        #pragma unroll
        for (int kk = 0; kk < 28; kk++) {
            unsigned long long a2 = Ar[kk];
            ffma2(acc[0], a2, B0[kk]);
            ffma2(acc[1], a2, B1[kk]);
            ffma2(acc[2], a2, B2[kk]);
            ffma2(acc[3], a2, B3[kk]);
        }
        if (it < 13) {
            #pragma unroll
            for (int m = 0; m < 7; m++) {
                int i = tid + 256 * m;
                int r = i / 56, k = i % 56;
                Ash[nxt][r][k] = ra[m];
                Bsh[nxt][r][k] = rb[m];
            }
        }
        __syncthreads();
    }
    #pragma unroll
    for (int i = 0; i < 4; i++) {
        int g = g0 + wid + 8 * i;
        float2 f = upk2(acc[i]);
        g_gi[(tb0 + tb) * (3 * HID) + g] = f.x + f.y + bih[g];
    }
}

// =====================================================================
// Kernel 3: GRU, one 8-CTA cluster PER BATCH (8 clusters, 64 CTAs).
// CTA rank owns units j in [rank*32, rank*32+32). Thread (jl = tid>>3,
// ks = tid&7): W_hh slice in 48 f32x2 register pairs. gi slice for this
// (b, rank) preloaded into smem. h in local smem (swizzled), producers
// push h_new to all 8 peers via st.shared::cluster; barrier.cluster/step.
// =====================================================================
__global__ void __launch_bounds__(256, 1) __cluster_dims__(8, 1, 1)
gru_kernel(const float* __restrict__ Whh,
           const float* __restrict__ bhh,
           const float* __restrict__ Wout,
           const float* __restrict__ bout,
           float* __restrict__ out) {
    __shared__ float hs[2][264];     // double-buffered h (swizzled), 256+pad
    __shared__ float gis[TT][96];    // gi[t][g*32+jl] for this (b, rank)

    int tid  = threadIdx.x;
    int b    = blockIdx.x >> 3;      // batch = cluster id
    int rank = blockIdx.x & 7;       // cluster rank
    int jl   = tid >> 3;             // 0..31
    int ks   = tid & 7;              // 0..7
    int j    = rank * 32 + jl;       // owned hidden unit

    // --- W_hh slice into registers: gate g, k = ks*32 .. ks*32+31 ---
    unsigned long long wp[3][16];
    #pragma unroll
    for (int g = 0; g < 3; g++) {
        const ulonglong2* ws =
            (const ulonglong2*)(Whh + (long long)(g * HID + j) * HID + ks * 32);
        #pragma unroll
        for (int m = 0; m < 8; m++) {
            ulonglong2 v = ws[m];
            wp[g][2 * m]     = v.x;
            wp[g][2 * m + 1] = v.y;
        }
    }
    float bh0 = bhh[j], bh1 = bhh[HID + j], bh2 = bhh[2 * HID + j];
    float hpv = 0.0f;                // hprev for owned (b, j): scalar

    // --- preload gi slice: gis[t][g*32+jl'] = g_gi[(t*8+b)*768 + g*256 + rank*32 + jl'] ---
    #pragma unroll
    for (int i = tid; i < TT * 96; i += 256) {
        int t = i / 96, r = i % 96;
        int g = r >> 5, jj = r & 31;
        gis[t][r] = g_gi[(long long)(t * BB + b) * (3 * HID) + g * HID + rank * 32 + jj];
    }
    // zero both h buffers, then cluster-wide rendezvous
    for (int s = tid; s < 2 * 264; s += 256) (&hs[0][0])[s] = 0.0f;
    __syncthreads();
    cluster_sync_();

    for (int t = 0; t < TT; t++) {
        const unsigned long long* hb = (const unsigned long long*)hs[t & 1];

        // partial dots over k = ks*32..ks*32+31 (pairs p = 16*ks + i)
        unsigned long long a0 = 0, a1 = 0, a2 = 0;
        #pragma unroll
        for (int i = 0; i < 16; i++) {
            unsigned long long h2 = hb[(i << 3) | ks];
            ffma2(a0, wp[0][i], h2);
            ffma2(a1, wp[1][i], h2);
            ffma2(a2, wp[2][i], h2);
        }
        float2 f;
        f = upk2(a0);  float v0 = f.x + f.y;
        f = upk2(a1);  float v1 = f.x + f.y;
        f = upk2(a2);  float v2 = f.x + f.y;
        #pragma unroll
        for (int d = 4; d >= 1; d >>= 1) {
            v0 += __shfl_down_sync(0xffffffffu, v0, d, 8);
            v1 += __shfl_down_sync(0xffffffffu, v1, d, 8);
            v2 += __shfl_down_sync(0xffffffffu, v2, d, 8);
        }

        if (ks == 0) {
            float r = sigm(gis[t][jl]        + v0 + bh0);
            float z = sigm(gis[t][32 + jl]   + v1 + bh1);
            float n = tanh_fast(gis[t][64 + jl] + r * (v2 + bh2));
            float hnew = n + z * (hpv - n);
            hpv = hnew;
            // swizzled float index for h[j] in next buffer
            int p    = j >> 1;
            int slot = ((p & 15) << 3) | (p >> 4);
            int fidx = 2 * slot + (j & 1);
            uint32_t la = smem_u32(&hs[(t + 1) & 1][fidx]);
            #pragma unroll
            for (int pr = 0; pr < 8; pr++) st_cluster_f32(la, pr, hnew);
        }

        cluster_sync_();
    }

    // ---- output head: final h (t=16) in local hs[0] of every CTA.
    // CTA rank -> outputs o = rank*16 + ol; thread (ol = tid>>4, kq = tid&15)
    {
        int ol = tid >> 4;           // 0..15
        int kq = tid & 15;           // 0..15
        int o  = rank * 16 + ol;
        const float* wo = Wout + (long long)o * HID;
        float a = 0.0f;
        #pragma unroll
        for (int m = 0; m < 16; m++) {
            int k    = kq * 16 + m;
            int p    = k >> 1;
            int slot = ((p & 15) << 3) | (p >> 4);
            a += wo[k] * hs[0][2 * slot + (k & 1)];
        }
        a += __shfl_down_sync(0xffffffffu, a, 8, 16);
        a += __shfl_down_sync(0xffffffffu, a, 4, 16);
        a += __shfl_down_sync(0xffffffffu, a, 2, 16);
        a += __shfl_down_sync(0xffffffffu, a, 1, 16);
        if (kq == 0) out[b * OUTSZ + o] = a + bout[o];
    }
}

// =====================================================================
extern "C" void kernel_launch(void* const* d_in, const int* in_sizes, int n_in,
                              void* d_out, int out_size) {
    const float* x    = (const float*)d_in[0];
    const float* Wih  = (const float*)d_in[1];
    const float* Whh  = (const float*)d_in[2];
    const float* bih  = (const float*)d_in[3];
    const float* bhh  = (const float*)d_in[4];
    const float* Wout = (const float*)d_in[5];
    const float* bout = (const float*)d_in[6];
    float* out = (float*)d_out;

    pool_kernel<<<1792, 256>>>(x);                 // 14336 warps
    gi_kernel<<<dim3(24, 4), 256>>>(Wih, bih);
    gru_kernel<<<64, 256>>>(Whh, bhh, Wout, bout, out);   // 8 clusters x 8 CTAs
}

// round 7
// speedup vs baseline: 2.0413x; 1.0180x over previous
#include <cuda_runtime.h>
#include <cstdint>

#define HID   256
#define BB    8
#define TT    16
#define INSZ  784
#define OUTSZ 128

// scratch (no device allocs allowed)
__device__ float g_seq[TT * BB * INSZ];       // [t][b][784]
__device__ float g_gi [TT * BB * 3 * HID];    // [t][b][768]

// ---------------- f32x2 helpers ----------------
__device__ __forceinline__ unsigned long long pk2(float a, float b) {
    unsigned long long r;
    asm("mov.b64 %0, {%1,%2};" : "=l"(r) : "f"(a), "f"(b));
    return r;
}
__device__ __forceinline__ float2 upk2(unsigned long long v) {
    float2 f;
    asm("mov.b64 {%0,%1}, %2;" : "=f"(f.x), "=f"(f.y) : "l"(v));
    return f;
}
__device__ __forceinline__ void ffma2(unsigned long long& d,
                                      unsigned long long a,
                                      unsigned long long b) {
    asm("fma.rn.f32x2 %0, %1, %2, %0;" : "+l"(d) : "l"(a), "l"(b));
}
__device__ __forceinline__ uint32_t smem_u32(const void* p) {
    uint32_t a;
    asm("{ .reg .u64 t; cvta.to.shared.u64 t, %1; cvt.u32.u64 %0, t; }"
        : "=r"(a) : "l"(p));
    return a;
}
__device__ __forceinline__ void cluster_sync_() {
    asm volatile("barrier.cluster.arrive.aligned;" ::: "memory");
    asm volatile("barrier.cluster.wait.aligned;"   ::: "memory");
}
// async remote store with tx-completion on the target CTA's mbarrier
__device__ __forceinline__ void st_async_f32(uint32_t dst_local, uint32_t bar_local,
                                             int rank, float v) {
    asm volatile(
        "{ .reg .b32 rd, rb;\n\t"
        "mapa.shared::cluster.u32 rd, %0, %2;\n\t"
        "mapa.shared::cluster.u32 rb, %1, %2;\n\t"
        "st.async.shared::cluster.mbarrier::complete_tx::bytes.f32 [rd], %3, [rb];\n\t"
        "}"
        :: "r"(dst_local), "r"(bar_local), "r"(rank), "f"(v) : "memory");
}
__device__ __forceinline__ void mbar_init(uint32_t bar, unsigned cnt) {
    asm volatile("mbarrier.init.shared.b64 [%0], %1;" :: "r"(bar), "r"(cnt) : "memory");
}
__device__ __forceinline__ void mbar_expect_tx(uint32_t bar, unsigned bytes) {
    asm volatile("mbarrier.arrive.expect_tx.shared.b64 _, [%0], %1;"
                 :: "r"(bar), "r"(bytes) : "memory");
}
__device__ __forceinline__ void mbar_wait_parity(uint32_t bar, unsigned parity) {
    asm volatile(
        "{ .reg .pred P;\n\t"
        "WL%=:\n\t"
        "mbarrier.try_wait.parity.acquire.cluster.shared::cta.b64 P, [%0], %1, 0x989680;\n\t"
        "@P bra WD%=;\n\t"
        "bra WL%=;\n\t"
        "WD%=:\n\t"
        "}"
        :: "r"(bar), "r"(parity) : "memory");
}
__device__ __forceinline__ float sigm(float x) {
    return 1.0f / (1.0f + __expf(-x));
}
__device__ __forceinline__ float tanh_fast(float x) {
    return 2.0f / (1.0f + __expf(-2.0f * x)) - 1.0f;
}

// =====================================================================
// Kernel 1: fused 3D+2D adaptive avg pool (R6-proven, at DRAM roofline).
// =====================================================================
__global__ void pool_kernel(const float* __restrict__ x) {
    int gwarp = (blockIdx.x * blockDim.x + threadIdx.x) >> 5;
    int lane  = threadIdx.x & 31;

    int h2 = gwarp % 7;  int tmp = gwarp / 7;
    int d2 = tmp % 16;   tmp /= 16;
    int c  = tmp % 16;   tmp /= 16;
    int b  = tmp;        // 0..7

    const float* base = x + (((long long)(b * 16 + c) * 32 + d2 * 2) * 112
                             + h2 * 16) * 112;
    float acc0 = 0.0f, acc1 = 0.0f;
    if (lane < 28) {
        #pragma unroll
        for (int dd = 0; dd < 2; dd++) {
            #pragma unroll 8
            for (int hh = 0; hh < 16; hh += 2) {
                const float4* r0 = (const float4*)(base + dd * 12544 + hh * 112);
                const float4* r1 = (const float4*)(base + dd * 12544 + (hh + 1) * 112);
                float4 v0 = __ldcs(r0 + lane);
                float4 v1 = __ldcs(r1 + lane);
                acc0 += (v0.x + v0.y) + (v0.z + v0.w);
                acc1 += (v1.x + v1.y) + (v1.z + v1.w);
            }
        }
    }
    float acc = acc0 + acc1;
    acc += __shfl_down_sync(0xffffffffu, acc, 2);
    acc += __shfl_down_sync(0xffffffffu, acc, 1);
    if (lane < 28 && (lane & 3) == 0) {
        int w2 = lane >> 2;
        g_seq[(d2 * BB + b) * INSZ + c * 49 + h2 * 7 + w2] = acc * (1.0f / 512.0f);
    }
}

// =====================================================================
// Kernel 2: gi = seq @ W_ih^T + b_ih (R6-proven double-buffered version).
// =====================================================================
__global__ void gi_kernel(const float* __restrict__ Wih,
                          const float* __restrict__ bih) {
    __shared__ __align__(16) float Ash[2][32][58];
    __shared__ __align__(16) float Bsh[2][32][58];

    int tid = threadIdx.x;
    int g0  = blockIdx.x * 32;
    int tb0 = blockIdx.y * 32;
    int tb  = tid & 31;
    int wid = tid >> 5;               // 0..7

    #pragma unroll
    for (int m = 0; m < 7; m++) {
        int i = tid + 256 * m;
        int r = i / 56, k = i % 56;
        Ash[0][r][k] = g_seq[(tb0 + r) * INSZ + k];
        Bsh[0][r][k] = Wih[(long long)(g0 + r) * INSZ + k];
    }
    __syncthreads();

    unsigned long long acc[4] = {0ull, 0ull, 0ull, 0ull};
    float ra[7], rb[7];

    for (int it = 0; it < 14; it++) {
        int cur = it & 1, nxt = cur ^ 1;
        if (it < 13) {
            int k0 = (it + 1) * 56;
            #pragma unroll
            for (int m = 0; m < 7; m++) {
                int i = tid + 256 * m;
                int r = i / 56, k = i % 56;
                ra[m] = g_seq[(tb0 + r) * INSZ + k0 + k];
                rb[m] = Wih[(long long)(g0 + r) * INSZ + k0 + k];
            }
        }
        const unsigned long long* Ar = (const unsigned long long*)Ash[cur][tb];
        const unsigned long long* B0 = (const unsigned long long*)Bsh[cur][wid];
        const unsigned long long* B1 = (const unsigned long long*)Bsh[cur][wid + 8];
        const unsigned long long* B2 = (const unsigned long long*)Bsh[cur][wid + 16];
        const unsigned long long* B3 = (const unsigned long long*)Bsh[cur][wid + 24];
        #pragma unroll
        for (int kk = 0; kk < 28; kk++) {
            unsigned long long a2 = Ar[kk];
            ffma2(acc[0], a2, B0[kk]);
            ffma2(acc[1], a2, B1[kk]);
            ffma2(acc[2], a2, B2[kk]);
            ffma2(acc[3], a2, B3[kk]);
        }
        if (it < 13) {
            #pragma unroll
            for (int m = 0; m < 7; m++) {
                int i = tid + 256 * m;
                int r = i / 56, k = i % 56;
                Ash[nxt][r][k] = ra[m];
                Bsh[nxt][r][k] = rb[m];
            }
        }
        __syncthreads();
    }
    #pragma unroll
    for (int i = 0; i < 4; i++) {
        int g = g0 + wid + 8 * i;
        float2 f = upk2(acc[i]);
        g_gi[(tb0 + tb) * (3 * HID) + g] = f.x + f.y + bih[g];
    }
}

// =====================================================================
// Kernel 3: GRU, one 8-CTA cluster PER BATCH (8 clusters, 64 CTAs).
// mbarrier ping-pong + st.async tx protocol (no barrier.cluster/step):
//  - expect_tx for step s posted at iter s-1 top (before s-1 stores);
//    causality: any peer's step-s stores require all s-1 stores -> safe.
//  - h TRIPLE-buffered (max cross-CTA skew is 1 phase).
//  - butterfly shfl_xor: every thread holds identical gate sums,
//    computes gate math, and issues ONE st.async to peer rank=ks.
// =====================================================================
__global__ void __launch_bounds__(256, 1) __cluster_dims__(8, 1, 1)
gru_kernel(const float* __restrict__ Whh,
           const float* __restrict__ bhh,
           const float* __restrict__ Wout,
           const float* __restrict__ bout,
           float* __restrict__ out) {
    __shared__ float hs[3][264];     // triple-buffered h (swizzled), 256+pad
    __shared__ float gis[TT][96];    // gi[t][g*32+jl] for this (b, rank)
    __shared__ __align__(8) unsigned long long mbar[2];

    int tid  = threadIdx.x;
    int b    = blockIdx.x >> 3;      // batch = cluster id
    int rank = blockIdx.x & 7;       // cluster rank
    int jl   = tid >> 3;             // 0..31
    int ks   = tid & 7;              // 0..7
    int j    = rank * 32 + jl;       // owned hidden unit

    // --- W_hh slice into registers: gate g, k = ks*32 .. ks*32+31 ---
    unsigned long long wp[3][16];
    #pragma unroll
    for (int g = 0; g < 3; g++) {
        const ulonglong2* ws =
            (const ulonglong2*)(Whh + (long long)(g * HID + j) * HID + ks * 32);
        #pragma unroll
        for (int m = 0; m < 8; m++) {
            ulonglong2 v = ws[m];
            wp[g][2 * m]     = v.x;
            wp[g][2 * m + 1] = v.y;
        }
    }
    float bh0 = bhh[j], bh1 = bhh[HID + j], bh2 = bhh[2 * HID + j];

    // --- preload gi slice ---
    #pragma unroll
    for (int i = tid; i < TT * 96; i += 256) {
        int t = i / 96, r = i % 96;
        int g = r >> 5, jj = r & 31;
        gis[t][r] = g_gi[(long long)(t * BB + b) * (3 * HID) + g * HID + rank * 32 + jj];
    }
    // zero all 3 h buffers
    for (int s = tid; s < 3 * 264; s += 256) (&hs[0][0])[s] = 0.0f;

    uint32_t bar0 = smem_u32(&mbar[0]);
    uint32_t bar1 = smem_u32(&mbar[1]);
    if (tid == 0) {
        mbar_init(bar0, 1);
        mbar_init(bar1, 1);
        mbar_expect_tx(bar0, 1024);       // for step 0's stores
    }
    __syncthreads();
    cluster_sync_();                      // all barriers inited, buffers zeroed

    // swizzled float index for my j (store target in peer buffers)
    int p_    = j >> 1;
    int slot_ = ((p_ & 15) << 3) | (p_ >> 4);
    int fidx  = 2 * slot_ + (j & 1);

    float hpv = 0.0f;                     // hprev for (b, j): all ks identical

    for (int t = 0; t < TT; t++) {
        uint32_t barT = (t & 1) ? bar1 : bar0;
        if (tid == 0 && t < TT - 1)
            mbar_expect_tx((t & 1) ? bar0 : bar1, 1024);   // for step t+1

        const unsigned long long* hb = (const unsigned long long*)hs[t % 3];

        unsigned long long a0 = 0, a1 = 0, a2 = 0;
        #pragma unroll
        for (int i = 0; i < 16; i++) {
            unsigned long long h2 = hb[(i << 3) | ks];
            ffma2(a0, wp[0][i], h2);
            ffma2(a1, wp[1][i], h2);
            ffma2(a2, wp[2][i], h2);
        }
        float2 f;
        f = upk2(a0);  float v0 = f.x + f.y;
        f = upk2(a1);  float v1 = f.x + f.y;
        f = upk2(a2);  float v2 = f.x + f.y;
        #pragma unroll
        for (int d = 4; d >= 1; d >>= 1) {
            v0 += __shfl_xor_sync(0xffffffffu, v0, d, 8);
            v1 += __shfl_xor_sync(0xffffffffu, v1, d, 8);
            v2 += __shfl_xor_sync(0xffffffffu, v2, d, 8);
        }

        // gate math on ALL threads (bit-identical across ks)
        float r = sigm(gis[t][jl]      + v0 + bh0);
        float z = sigm(gis[t][32 + jl] + v1 + bh1);
        float n = tanh_fast(gis[t][64 + jl] + r * (v2 + bh2));
        float hnew = n + z * (hpv - n);
        hpv = hnew;

        __syncthreads();   // orders thread0's expect post before our stores

        // one async store per thread: h[j] -> peer rank=ks, buffer (t+1)%3
        uint32_t dst = smem_u32(&hs[(t + 1) % 3][fidx]);
        st_async_f32(dst, barT, ks, hnew);

        mbar_wait_parity(barT, (t >> 1) & 1);
    }

    // ---- output head: final h (t=16) is in hs[16%3 = 1] of every CTA.
    {
        int ol = tid >> 4;           // 0..15
        int kq = tid & 15;           // 0..15
        int o  = rank * 16 + ol;
        const float* wo = Wout + (long long)o * HID;
        float a = 0.0f;
        #pragma unroll
        for (int m = 0; m < 16; m++) {
            int k    = kq * 16 + m;
            int pp   = k >> 1;
            int sl   = ((pp & 15) << 3) | (pp >> 4);
            a += wo[k] * hs[1][2 * sl + (k & 1)];
        }
        a += __shfl_down_sync(0xffffffffu, a, 8, 16);
        a += __shfl_down_sync(0xffffffffu, a, 4, 16);
        a += __shfl_down_sync(0xffffffffu, a, 2, 16);
        a += __shfl_down_sync(0xffffffffu, a, 1, 16);
        if (kq == 0) out[b * OUTSZ + o] = a + bout[o];
    }
}

// =====================================================================
extern "C" void kernel_launch(void* const* d_in, const int* in_sizes, int n_in,
                              void* d_out, int out_size) {
    const float* x    = (const float*)d_in[0];
    const float* Wih  = (const float*)d_in[1];
    const float* Whh  = (const float*)d_in[2];
    const float* bih  = (const float*)d_in[3];
    const float* bhh  = (const float*)d_in[4];
    const float* Wout = (const float*)d_in[5];
    const float* bout = (const float*)d_in[6];
    float* out = (float*)d_out;

    pool_kernel<<<1792, 256>>>(x);                 // 14336 warps
    gi_kernel<<<dim3(24, 4), 256>>>(Wih, bih);
    gru_kernel<<<64, 256>>>(Whh, bhh, Wout, bout, out);   // 8 clusters x 8 CTAs
}